// round 1
// baseline (speedup 1.0000x reference)
#include <cuda_runtime.h>
#include <math_constants.h>
#include <cstdint>
#include <cstddef>

#define KSEL 32
#define MAXB 256
#define MAXN 200000

// Scratch (device globals: allocation-free per harness rules)
__device__ float g_S[(size_t)MAXB * (size_t)MAXN];  // s[b,n] = x2[n] - 2*q_b.x_n
__device__ float g_x2[MAXN];

// ---------------- row squared norms of X ----------------
__global__ void x2_kernel(const float* __restrict__ X, int N, int K) {
    int warp = (int)((blockIdx.x * blockDim.x + threadIdx.x) >> 5);
    int lane = threadIdx.x & 31;
    if (warp >= N) return;
    const float* row = X + (size_t)warp * K;
    float s = 0.f;
    for (int k = lane; k < K; k += 32) { float v = row[k]; s = fmaf(v, v, s); }
    #pragma unroll
    for (int off = 16; off > 0; off >>= 1) s += __shfl_xor_sync(0xffffffffu, s, off);
    if (lane == 0) g_x2[warp] = s;
}

// ---------------- tiled fp32 GEMM: s = x2 - 2 * Q @ X^T ----------------
// BM=BN=128, BK=16, 256 threads, 8x8 per thread
__global__ __launch_bounds__(256)
void gemm_kernel(const float* __restrict__ Q, const float* __restrict__ X,
                 int B, int N, int K)
{
    __shared__ float As[16][128 + 4];
    __shared__ float Bs[16][128 + 4];
    const int tid  = threadIdx.x;
    const int bn   = blockIdx.x * 128;
    const int bm   = blockIdx.y * 128;
    const int tx   = tid & 15;        // n-direction
    const int ty   = tid >> 4;        // m-direction
    const int lrow = tid >> 2;        // 0..63
    const int lcol = (tid & 3) << 2;  // 0,4,8,12

    float acc[8][8];
    #pragma unroll
    for (int i = 0; i < 8; i++)
        #pragma unroll
        for (int j = 0; j < 8; j++) acc[i][j] = 0.f;

    const float4 z4 = make_float4(0.f, 0.f, 0.f, 0.f);
    float4 ar[2], br[2];

    // prologue: load k-tile 0
    #pragma unroll
    for (int s = 0; s < 2; s++) {
        int m = bm + lrow + s * 64;
        int n = bn + lrow + s * 64;
        ar[s] = (m < B) ? *(const float4*)(Q + (size_t)m * K + lcol) : z4;
        br[s] = (n < N) ? *(const float4*)(X + (size_t)n * K + lcol) : z4;
    }
    #pragma unroll
    for (int s = 0; s < 2; s++) {
        int r = lrow + s * 64;
        As[lcol + 0][r] = ar[s].x; As[lcol + 1][r] = ar[s].y;
        As[lcol + 2][r] = ar[s].z; As[lcol + 3][r] = ar[s].w;
        Bs[lcol + 0][r] = br[s].x; Bs[lcol + 1][r] = br[s].y;
        Bs[lcol + 2][r] = br[s].z; Bs[lcol + 3][r] = br[s].w;
    }
    __syncthreads();

    for (int k0 = 0; k0 < K; k0 += 16) {
        bool more = (k0 + 16) < K;
        if (more) {
            int kn = k0 + 16;
            #pragma unroll
            for (int s = 0; s < 2; s++) {
                int m = bm + lrow + s * 64;
                int n = bn + lrow + s * 64;
                ar[s] = (m < B) ? *(const float4*)(Q + (size_t)m * K + kn + lcol) : z4;
                br[s] = (n < N) ? *(const float4*)(X + (size_t)n * K + kn + lcol) : z4;
            }
        }
        #pragma unroll
        for (int kk = 0; kk < 16; kk++) {
            float4 a0 = *(const float4*)&As[kk][ty * 8];
            float4 a1 = *(const float4*)&As[kk][ty * 8 + 4];
            float4 b0 = *(const float4*)&Bs[kk][tx * 8];
            float4 b1 = *(const float4*)&Bs[kk][tx * 8 + 4];
            float a[8]  = {a0.x, a0.y, a0.z, a0.w, a1.x, a1.y, a1.z, a1.w};
            float bf[8] = {b0.x, b0.y, b0.z, b0.w, b1.x, b1.y, b1.z, b1.w};
            #pragma unroll
            for (int i = 0; i < 8; i++)
                #pragma unroll
                for (int j = 0; j < 8; j++)
                    acc[i][j] = fmaf(a[i], bf[j], acc[i][j]);
        }
        __syncthreads();
        if (more) {
            #pragma unroll
            for (int s = 0; s < 2; s++) {
                int r = lrow + s * 64;
                As[lcol + 0][r] = ar[s].x; As[lcol + 1][r] = ar[s].y;
                As[lcol + 2][r] = ar[s].z; As[lcol + 3][r] = ar[s].w;
                Bs[lcol + 0][r] = br[s].x; Bs[lcol + 1][r] = br[s].y;
                Bs[lcol + 2][r] = br[s].z; Bs[lcol + 3][r] = br[s].w;
            }
            __syncthreads();
        }
    }

    // epilogue: s = x2[n] - 2*dot
    int n0 = bn + tx * 8;
    float xv[8];
    #pragma unroll
    for (int j = 0; j < 8; j++) xv[j] = (n0 + j < N) ? g_x2[n0 + j] : 0.f;

    bool vec_ok = (n0 + 7 < N) && ((N & 3) == 0);
    #pragma unroll
    for (int i = 0; i < 8; i++) {
        int m = bm + ty * 8 + i;
        if (m >= B) continue;
        float* srow = g_S + (size_t)m * N + n0;
        if (vec_ok) {
            float4 v0 = make_float4(fmaf(-2.f, acc[i][0], xv[0]), fmaf(-2.f, acc[i][1], xv[1]),
                                    fmaf(-2.f, acc[i][2], xv[2]), fmaf(-2.f, acc[i][3], xv[3]));
            float4 v1 = make_float4(fmaf(-2.f, acc[i][4], xv[4]), fmaf(-2.f, acc[i][5], xv[5]),
                                    fmaf(-2.f, acc[i][6], xv[6]), fmaf(-2.f, acc[i][7], xv[7]));
            *(float4*)(srow)     = v0;
            *(float4*)(srow + 4) = v1;
        } else {
            for (int j = 0; j < 8; j++)
                if (n0 + j < N) srow[j] = fmaf(-2.f, acc[i][j], xv[j]);
        }
    }
}

// ---------------- per-query top-32 + local layer + prefix softmax ----------------
__global__ __launch_bounds__(256)
void topk_kernel(const float* __restrict__ Q, const int* __restrict__ qsys,
                 const float* __restrict__ Y, const int* __restrict__ sys,
                 const float* __restrict__ W, const float* __restrict__ bias,
                 float* __restrict__ out, int B, int N, int K)
{
    const int b   = blockIdx.x;
    const int tid = threadIdx.x;

    __shared__ float red[256];
    __shared__ unsigned long long skey[256];
    __shared__ float selv[KSEL];
    __shared__ int   seli[KSEL];

    // q2 = ||q_b||^2
    float q2p = 0.f;
    const float* qrow = Q + (size_t)b * K;
    for (int k = tid; k < K; k += 256) { float v = qrow[k]; q2p = fmaf(v, v, q2p); }
    red[tid] = q2p;
    __syncthreads();
    for (int s = 128; s > 0; s >>= 1) {
        if (tid < s) red[tid] += red[tid + s];
        __syncthreads();
    }
    float q2 = red[0];
    __syncthreads();

    // per-thread sorted top-32 over strided partition
    float vals[KSEL];
    int   ids[KSEL];
    #pragma unroll
    for (int i = 0; i < KSEL; i++) { vals[i] = CUDART_INF_F; ids[i] = 0x7fffffff; }
    const float* srow = g_S + (size_t)b * N;
    for (int n = tid; n < N; n += 256) {
        float v = srow[n];
        if (v < vals[KSEL - 1]) {
            int pos = KSEL - 1;
            while (pos > 0 && vals[pos - 1] > v) {
                vals[pos] = vals[pos - 1]; ids[pos] = ids[pos - 1]; pos--;
            }
            vals[pos] = v; ids[pos] = n;
        }
    }

    // tournament merge: 32 rounds of block-wide min over (value, index) keys
    int head = 0;
    for (int r = 0; r < KSEL; r++) {
        unsigned long long key;
        if (head < KSEL) {
            unsigned u = __float_as_uint(vals[head]);
            u = (u & 0x80000000u) ? ~u : (u | 0x80000000u);   // order-preserving map
            key = ((unsigned long long)u << 32) | (unsigned)ids[head];
        } else {
            key = ~0ULL;
        }
        skey[tid] = key;
        __syncthreads();
        for (int s = 128; s > 0; s >>= 1) {
            if (tid < s && skey[tid + s] < skey[tid]) skey[tid] = skey[tid + s];
            __syncthreads();
        }
        unsigned long long wk = skey[0];
        __syncthreads();
        if (key == wk) head++;   // indices unique -> exactly one winner advances
        if (tid == 0) {
            unsigned u = (unsigned)(wk >> 32);
            u = (u & 0x80000000u) ? (u & 0x7fffffffu) : ~u;   // inverse map
            selv[r] = __uint_as_float(u);
            seli[r] = (int)(wk & 0xffffffffu);
        }
        __syncthreads();
    }

    // finalize (warp 0, lane i == neighbor rank i)
    if (tid < KSEL) {
        float d2v = q2 + selv[tid];
        int   idx = seli[tid];
        float sc  = Y[idx];
        int   ls  = sys[idx];
        int   qs  = qsys[b];
        float nd  = (ls == qs) ? fmaf(d2v, W[1], bias[1]) : fmaf(d2v, W[0], bias[0]);
        float neg = -nd;
        float mmax = neg;
        #pragma unroll
        for (int off = 16; off > 0; off >>= 1)
            mmax = fmaxf(mmax, __shfl_xor_sync(0xffffffffu, mmax, off));
        float w  = expf(neg - mmax);
        float ws = w * sc;
        float cw = w, cws = ws;
        #pragma unroll
        for (int off = 1; off < KSEL; off <<= 1) {
            float tw  = __shfl_up_sync(0xffffffffu, cw,  off);
            float tws = __shfl_up_sync(0xffffffffu, cws, off);
            if (tid >= off) { cw += tw; cws += tws; }
        }
        out[(size_t)b * KSEL + tid] = nd;
        out[(size_t)B * KSEL + (size_t)b * KSEL + tid] = cws / cw;
    }
}

extern "C" void kernel_launch(void* const* d_in, const int* in_sizes, int n_in,
                              void* d_out, int out_size)
{
    const float* Q    = (const float*)d_in[0];
    const int*   qsys = (const int*)  d_in[1];
    const float* X    = (const float*)d_in[2];
    const float* Y    = (const float*)d_in[3];
    const int*   sys  = (const int*)  d_in[4];
    const float* W    = (const float*)d_in[5];
    const float* bias = (const float*)d_in[6];
    float* out = (float*)d_out;

    int B = in_sizes[1];
    int N = in_sizes[3];
    int K = in_sizes[0] / B;

    // 1) row norms of X
    x2_kernel<<<(N + 7) / 8, 256>>>(X, N, K);
    // 2) distance GEMM -> scratch
    dim3 grid((N + 127) / 128, (B + 127) / 128);
    gemm_kernel<<<grid, 256>>>(Q, X, B, N, K);
    // 3) top-32 + epilogue
    topk_kernel<<<B, 256>>>(Q, qsys, Y, sys, W, bias, out, B, N, K);
}